// round 9
// baseline (speedup 1.0000x reference)
#include <cuda_runtime.h>
#include <math.h>
#include <stdint.h>

// ---------------- problem constants ----------------
#define BB    32
#define TTOK  256
#define TT    257          // T_TOK + 1 (class token)
#define CC    1024
#define NHH   16
#define HDD   64
#define LL    12
#define VV    16384
#define MM    (BB * TT)    // 8224 rows
#define C4    (4 * CC)     // 4096
#define LN_EPS 1e-5f
#define ATT_SCALE 0.125f   // 1/sqrt(64)

// ---------------- scratch (device globals; no allocation allowed) ----------------
__device__ float g_x  [(size_t)MM * CC];
__device__ float g_h  [(size_t)MM * CC];
__device__ float g_q  [(size_t)MM * CC];
__device__ float g_k  [(size_t)MM * CC];
__device__ float g_v  [(size_t)MM * CC];
__device__ float g_y  [(size_t)MM * CC];
__device__ float g_att[(size_t)BB * NHH * TT * TT];
__device__ float g_mlp[(size_t)MM * C4];

// ---------------- tf32 helpers ----------------
__device__ __forceinline__ uint32_t f2tf32(float f) {
    uint32_t u;
    asm("cvt.rna.tf32.f32 %0, %1;" : "=r"(u) : "f"(f));
    return u;
}

// A fragment arrives as uint4 in SMEM word order {a0, a2, a1, a3};
// permute to mma order (a0,a1,a2,a3) = (x, z, y, w) at the asm operand level.
__device__ __forceinline__ void mma_tf32_v(float* c, const uint4& a,
                                           uint32_t b0, uint32_t b1) {
    asm volatile(
        "mma.sync.aligned.m16n8k8.row.col.f32.tf32.tf32.f32 "
        "{%0,%1,%2,%3}, {%4,%5,%6,%7}, {%8,%9}, {%0,%1,%2,%3};\n"
        : "+f"(c[0]), "+f"(c[1]), "+f"(c[2]), "+f"(c[3])
        : "r"(a.x), "r"(a.z), "r"(a.y), "r"(a.w), "r"(b0), "r"(b1));
}

// ---------------- embedding ----------------
__global__ void __launch_bounds__(256) embed_kernel(
    const float* __restrict__ tok_emb, const float* __restrict__ cls_emb,
    const float* __restrict__ pos_emb, const int* __restrict__ idx_tok,
    const int* __restrict__ idx_cls, float* __restrict__ x)
{
    int bt = blockIdx.x;
    int b = bt / TT, t = bt % TT;
    const float* src;
    if (t == 0) src = cls_emb + (size_t)idx_cls[b] * CC;
    else        src = tok_emb + (size_t)idx_tok[b * TTOK + (t - 1)] * CC;
    const float4* s4 = (const float4*)src;
    const float4* p4 = (const float4*)(pos_emb + (size_t)t * CC);
    float4*       o4 = (float4*)(x + (size_t)bt * CC);
    int tid = threadIdx.x;
    float4 a = s4[tid], p = p4[tid];
    a.x += p.x; a.y += p.y; a.z += p.z; a.w += p.w;
    o4[tid] = a;
}

// ---------------- LayerNorm ----------------
__global__ void __launch_bounds__(256) layernorm_kernel(
    const float* __restrict__ x, const float* __restrict__ w,
    const float* __restrict__ b, float* __restrict__ out)
{
    int row = blockIdx.x;
    int tid = threadIdx.x;
    const float4* x4 = (const float4*)(x + (size_t)row * CC);
    float4 v = x4[tid];
    float s  = v.x + v.y + v.z + v.w;
    float ss = v.x * v.x + v.y * v.y + v.z * v.z + v.w * v.w;
    #pragma unroll
    for (int o = 16; o > 0; o >>= 1) {
        s  += __shfl_xor_sync(0xffffffffu, s,  o);
        ss += __shfl_xor_sync(0xffffffffu, ss, o);
    }
    __shared__ float rs[8], rss[8], bc[2];
    int wid = tid >> 5, lane = tid & 31;
    if (lane == 0) { rs[wid] = s; rss[wid] = ss; }
    __syncthreads();
    if (wid == 0) {
        float a  = (lane < 8) ? rs[lane]  : 0.f;
        float a2 = (lane < 8) ? rss[lane] : 0.f;
        #pragma unroll
        for (int o = 4; o > 0; o >>= 1) {
            a  += __shfl_xor_sync(0xffffffffu, a,  o);
            a2 += __shfl_xor_sync(0xffffffffu, a2, o);
        }
        if (lane == 0) { bc[0] = a; bc[1] = a2; }
    }
    __syncthreads();
    float mean = bc[0] * (1.0f / CC);
    float var  = bc[1] * (1.0f / CC) - mean * mean;
    float inv  = rsqrtf(var + LN_EPS);
    const float4* w4 = (const float4*)w;
    const float4* b4 = (const float4*)b;
    float4 wv = w4[tid], bv = b4[tid], o;
    o.x = (v.x - mean) * inv * wv.x + bv.x;
    o.y = (v.y - mean) * inv * wv.y + bv.y;
    o.z = (v.z - mean) * inv * wv.z + bv.z;
    o.w = (v.w - mean) * inv * wv.w + bv.w;
    ((float4*)(out + (size_t)row * CC))[tid] = o;
}

// ---------------- TF32 tensor-core GEMM, fragment-major SMEM, STS.64 stores --------
// C = epi(A @ W^T + bias). A: MxK fp32 row-major, W: NxK fp32 row-major.
// Block 128x128, BK=16, 8 warps (4m x 2n), warp tile 32x64.
// A region ((slice*2+ks)*2+subm)*128 words; element (r16,k8):
//   lane=(r16&7)*4+(k8&3), chunk=lane^(lane>>3), word=chunk*4 + (r16>>3)*2 + (k8>>2)
//   (word order within chunk = {a0,a2,a1,a3}; consumer permutes regs)
// B region (p*2+ks)*128 words; element (col,k8):
//   lane=(col&7)*4+(k8&3), chunk=lane^(lane>>3), word=chunk*4 + ((col>>3)&1)*2 + (k8>>2)
// Producer: each thread's (k, k+4) pair -> adjacent words -> one STS.64.
// Consumer: LDS.128 at chunk' = lane^(lane>>3) — conflict-free.
template <bool RES, bool GELU_>
__global__ void __launch_bounds__(256, 2) tgemm_nt(
    const float* __restrict__ A, const float* __restrict__ W,
    const float* __restrict__ bias, const float* __restrict__ res,
    float* __restrict__ C, int M, int N, int K)
{
    __shared__ uint32_t As[2][2048];
    __shared__ uint32_t Bs[2][2048];

    int bm = blockIdx.y * 128;
    int bn = blockIdx.x * 128;
    int tid = threadIdx.x;
    int lane = tid & 31;
    int wid  = tid >> 5;
    int g  = lane >> 2;
    int t4 = lane & 3;
    int wm = (wid & 3) * 32;
    int wn = (wid >> 2) * 64;

    // loader mapping
    int lrow = tid >> 1;           // 0..127
    int lks  = tid & 1;            // which 8-k half of the 16-k slab
    const float* Arow = A + (size_t)(bm + lrow) * K;
    const float* Wrow = W + (size_t)(bn + lrow) * K;
    bool a_ok = (bm + lrow) < M;

    // loader precomputed fragment-address constants
    int a_region = (((lrow >> 5) * 2 + lks) * 2 + ((lrow >> 4) & 1)) * 128;
    int a_laneB  = (lrow & 7) * 4;
    int a_c      = (lrow & 7) >> 1;
    int a_r2     = ((lrow >> 3) & 1) * 2;   // word pair base for A (r>>3)*2
    int b_region = ((lrow >> 4) * 2 + lks) * 128;
    int b_laneB  = a_laneB;        // (lrow&7)*4
    int b_c      = a_c;
    int b_r2     = ((lrow >> 3) & 1) * 2;   // word pair base for B

    // consumer constants
    int chunkOff = (lane ^ (lane >> 3)) * 4;
    int aRegBase = (wid & 3) * 512;           // slice*2*2*128
    int bRegBase = (wid >> 2) * 4 * 256;      // p start * 2 * 128

    float acc[2][8][4];
    #pragma unroll
    for (int im = 0; im < 2; im++)
        #pragma unroll
        for (int in_ = 0; in_ < 8; in_++)
            #pragma unroll
            for (int r = 0; r < 4; r++) acc[im][in_][r] = 0.f;

    // scatter one 8-k run into fragment layout; (k, k+4) fused into STS.64
#define STORE_A(buf_, v0, v1) {                                              \
        float _q0[4] = {(v0).x,(v0).y,(v0).z,(v0).w};                        \
        float _q1[4] = {(v1).x,(v1).y,(v1).z,(v1).w};                        \
        _Pragma("unroll")                                                    \
        for (int _t = 0; _t < 4; _t++) {                                     \
            int _ch = (a_laneB + _t) ^ a_c;                                  \
            uint2 _p = make_uint2(f2tf32(_q0[_t]), f2tf32(_q1[_t]));         \
            *(uint2*)&As[buf_][a_region + _ch*4 + a_r2] = _p;                \
        } }
#define STORE_B(buf_, v0, v1) {                                              \
        float _q0[4] = {(v0).x,(v0).y,(v0).z,(v0).w};                        \
        float _q1[4] = {(v1).x,(v1).y,(v1).z,(v1).w};                        \
        _Pragma("unroll")                                                    \
        for (int _t = 0; _t < 4; _t++) {                                     \
            int _ch = (b_laneB + _t) ^ b_c;                                  \
            uint2 _p = make_uint2(f2tf32(_q0[_t]), f2tf32(_q1[_t]));         \
            *(uint2*)&Bs[buf_][b_region + _ch*4 + b_r2] = _p;                \
        } }

    // ---- preload tile 0 ----
    {
        int kbase = lks * 8;
        float4 a0 = make_float4(0.f,0.f,0.f,0.f), a1 = a0;
        if (a_ok) {
            a0 = *(const float4*)&Arow[kbase];
            a1 = *(const float4*)&Arow[kbase + 4];
        }
        float4 w0 = *(const float4*)&Wrow[kbase];
        float4 w1 = *(const float4*)&Wrow[kbase + 4];
        STORE_A(0, a0, a1);
        STORE_B(0, w0, w1);
    }
    __syncthreads();

    int buf = 0;
    for (int k0 = 0; k0 < K; k0 += 16) {
        // register prefetch of next K-slab
        float4 pa0, pa1, pw0, pw1;
        bool has_next = (k0 + 16 < K);
        if (has_next) {
            int kn = k0 + 16 + lks * 8;
            pa0 = make_float4(0.f,0.f,0.f,0.f); pa1 = pa0;
            if (a_ok) {
                pa0 = *(const float4*)&Arow[kn];
                pa1 = *(const float4*)&Arow[kn + 4];
            }
            pw0 = *(const float4*)&Wrow[kn];
            pw1 = *(const float4*)&Wrow[kn + 4];
        }

        // ---- compute: 2 k-steps of 8 ----
        #pragma unroll
        for (int ks = 0; ks < 2; ks++) {
            uint4 afv[2];
            #pragma unroll
            for (int subm = 0; subm < 2; subm++)
                afv[subm] = *(const uint4*)&As[buf][aRegBase + (ks*2 + subm)*128 + chunkOff];
            uint4 bfv[4];
            #pragma unroll
            for (int pl = 0; pl < 4; pl++)
                bfv[pl] = *(const uint4*)&Bs[buf][bRegBase + (pl*2 + ks)*128 + chunkOff];

            #pragma unroll
            for (int pl = 0; pl < 4; pl++) {
                mma_tf32_v(acc[0][2*pl+0], afv[0], bfv[pl].x, bfv[pl].y);
                mma_tf32_v(acc[1][2*pl+0], afv[1], bfv[pl].x, bfv[pl].y);
                mma_tf32_v(acc[0][2*pl+1], afv[0], bfv[pl].z, bfv[pl].w);
                mma_tf32_v(acc[1][2*pl+1], afv[1], bfv[pl].z, bfv[pl].w);
            }
        }

        if (has_next) {
            int nb = buf ^ 1;
            STORE_A(nb, pa0, pa1);
            STORE_B(nb, pw0, pw1);
            __syncthreads();
            buf = nb;
        }
    }
#undef STORE_A
#undef STORE_B

    // ---- epilogue ----
    #pragma unroll
    for (int im = 0; im < 2; im++) {
        int r0 = bm + wm + im * 16 + g;
        #pragma unroll
        for (int in_ = 0; in_ < 8; in_++) {
            int col = bn + wn + in_ * 8 + t4 * 2;
            float bx = 0.f, by = 0.f;
            if (bias) { bx = bias[col]; by = bias[col + 1]; }
            #pragma unroll
            for (int half = 0; half < 2; half++) {
                int row = r0 + half * 8;
                if (row >= M) continue;
                float vx = acc[im][in_][half * 2 + 0] + bx;
                float vy = acc[im][in_][half * 2 + 1] + by;
                if (GELU_) {
                    vx = 0.5f * vx * (1.f + erff(vx * 0.70710678118f));
                    vy = 0.5f * vy * (1.f + erff(vy * 0.70710678118f));
                }
                if (RES) {
                    float2 rv = *(const float2*)&res[(size_t)row * N + col];
                    vx += rv.x; vy += rv.y;
                }
                float2 o = make_float2(vx, vy);
                *(float2*)&C[(size_t)row * N + col] = o;
            }
        }
    }
}

// ---------------- attention scores (fp32) ----------------
__global__ void __launch_bounds__(256) attn_scores_kernel(
    const float* __restrict__ q, const float* __restrict__ k, float* __restrict__ att)
{
    int jt = blockIdx.x, it = blockIdx.y;
    if (jt > it) return;
    int bh = blockIdx.z;
    int b = bh / NHH, h = bh % NHH;
    __shared__ float Qs[32][65];
    __shared__ float Ks[32][65];
    int tid = threadIdx.x;

    #pragma unroll
    for (int rep = 0; rep < 2; rep++) {
        int f = tid + rep * 256;
        int row = f >> 4;
        int c4  = (f & 15) * 4;
        {
            int i = it * 32 + row;
            float4 v = make_float4(0.f, 0.f, 0.f, 0.f);
            if (i < TT) v = *(const float4*)&q[(((size_t)b * TT + i) * NHH + h) * HDD + c4];
            Qs[row][c4+0]=v.x; Qs[row][c4+1]=v.y; Qs[row][c4+2]=v.z; Qs[row][c4+3]=v.w;
        }
        {
            int j = jt * 32 + row;
            float4 v = make_float4(0.f, 0.f, 0.f, 0.f);
            if (j < TT) v = *(const float4*)&k[(((size_t)b * TT + j) * NHH + h) * HDD + c4];
            Ks[row][c4+0]=v.x; Ks[row][c4+1]=v.y; Ks[row][c4+2]=v.z; Ks[row][c4+3]=v.w;
        }
    }
    __syncthreads();

    int il = tid >> 3;
    int jb = (tid & 7) * 4;
    float a0 = 0.f, a1 = 0.f, a2 = 0.f, a3 = 0.f;
    #pragma unroll
    for (int kk = 0; kk < 64; kk++) {
        float qv = Qs[il][kk];
        a0 = fmaf(qv, Ks[jb + 0][kk], a0);
        a1 = fmaf(qv, Ks[jb + 1][kk], a1);
        a2 = fmaf(qv, Ks[jb + 2][kk], a2);
        a3 = fmaf(qv, Ks[jb + 3][kk], a3);
    }
    int i = it * 32 + il;
    if (i < TT) {
        size_t base = ((size_t)bh * TT + i) * TT;
        float r[4] = {a0, a1, a2, a3};
        #pragma unroll
        for (int u = 0; u < 4; u++) {
            int j = jt * 32 + jb + u;
            if (j < TT && j <= i) att[base + j] = r[u] * ATT_SCALE;
        }
    }
}

// ---------------- causal softmax ----------------
__global__ void __launch_bounds__(128) softmax_kernel(float* __restrict__ att)
{
    int row = blockIdx.x * 4 + (threadIdx.x >> 5);
    if (row >= BB * NHH * TT) return;
    int lane = threadIdx.x & 31;
    int i = row % TT;
    float* p = att + (size_t)row * TT;
    int len = i + 1;
    float m = -3.4e38f;
    for (int j = lane; j < len; j += 32) m = fmaxf(m, p[j]);
    #pragma unroll
    for (int o = 16; o > 0; o >>= 1) m = fmaxf(m, __shfl_xor_sync(0xffffffffu, m, o));
    float s = 0.f;
    for (int j = lane; j < len; j += 32) { float e = expf(p[j] - m); p[j] = e; s += e; }
    #pragma unroll
    for (int o = 16; o > 0; o >>= 1) s += __shfl_xor_sync(0xffffffffu, s, o);
    float inv = 1.f / s;
    for (int j = lane; j < TT; j += 32) p[j] = (j < len) ? p[j] * inv : 0.f;
}

// ---------------- AV (fp32) ----------------
__global__ void __launch_bounds__(256) attn_av_kernel(
    const float* __restrict__ att, const float* __restrict__ v, float* __restrict__ y)
{
    int it = blockIdx.x, dt = blockIdx.y, bh = blockIdx.z;
    int b = bh / NHH, h = bh % NHH;
    __shared__ float As[32][33];
    __shared__ float Vs[32][33];
    int tid = threadIdx.x;
    int il = tid >> 3;
    int db = (tid & 7) * 4;
    float acc0 = 0.f, acc1 = 0.f, acc2 = 0.f, acc3 = 0.f;

    for (int j0 = 0; j0 < TT; j0 += 32) {
        {
            int r  = tid >> 3;
            int cb = (tid & 7) * 4;
            int i  = it * 32 + r;
            #pragma unroll
            for (int u = 0; u < 4; u++) {
                int j = j0 + cb + u;
                As[r][cb + u] = (i < TT && j < TT) ? att[((size_t)bh * TT + i) * TT + j] : 0.f;
            }
            int jr = j0 + r;
            float4 vv = make_float4(0.f, 0.f, 0.f, 0.f);
            if (jr < TT)
                vv = *(const float4*)&v[(((size_t)b * TT + jr) * NHH + h) * HDD + dt * 32 + cb];
            Vs[r][cb+0]=vv.x; Vs[r][cb+1]=vv.y; Vs[r][cb+2]=vv.z; Vs[r][cb+3]=vv.w;
        }
        __syncthreads();
        #pragma unroll
        for (int jj = 0; jj < 32; jj++) {
            float a = As[il][jj];
            acc0 = fmaf(a, Vs[jj][db + 0], acc0);
            acc1 = fmaf(a, Vs[jj][db + 1], acc1);
            acc2 = fmaf(a, Vs[jj][db + 2], acc2);
            acc3 = fmaf(a, Vs[jj][db + 3], acc3);
        }
        __syncthreads();
    }
    int i = it * 32 + il;
    if (i < TT) {
        size_t base = (((size_t)b * TT + i) * NHH + h) * HDD + dt * 32 + db;
        float4 o = make_float4(acc0, acc1, acc2, acc3);
        *(float4*)&y[base] = o;
    }
}

// ---------------- host orchestration ----------------
extern "C" void kernel_launch(void* const* d_in, const int* in_sizes, int n_in,
                              void* d_out, int out_size)
{
    const float* tok_emb = (const float*)d_in[0];
    const float* cls_emb = (const float*)d_in[1];
    const float* pos_emb = (const float*)d_in[2];
    const float* ln1_w   = (const float*)d_in[3];
    const float* ln1_b   = (const float*)d_in[4];
    const float* Wq      = (const float*)d_in[5];
    const float* bq      = (const float*)d_in[6];
    const float* Wk      = (const float*)d_in[7];
    const float* bk      = (const float*)d_in[8];
    const float* Wv      = (const float*)d_in[9];
    const float* bv      = (const float*)d_in[10];
    const float* Wo      = (const float*)d_in[11];
    const float* bo      = (const float*)d_in[12];
    const float* ln2_w   = (const float*)d_in[13];
    const float* ln2_b   = (const float*)d_in[14];
    const float* W1      = (const float*)d_in[15];
    const float* b1      = (const float*)d_in[16];
    const float* W2      = (const float*)d_in[17];
    const float* b2      = (const float*)d_in[18];
    const float* lnf_w   = (const float*)d_in[19];
    const float* lnf_b   = (const float*)d_in[20];
    const int* idx_tok   = (const int*)d_in[21];
    const int* idx_cls   = (const int*)d_in[22];
    float* out = (float*)d_out;

    float *X, *H, *Q, *K, *V, *Y, *ATT, *MLP;
    cudaGetSymbolAddress((void**)&X,   g_x);
    cudaGetSymbolAddress((void**)&H,   g_h);
    cudaGetSymbolAddress((void**)&Q,   g_q);
    cudaGetSymbolAddress((void**)&K,   g_k);
    cudaGetSymbolAddress((void**)&V,   g_v);
    cudaGetSymbolAddress((void**)&Y,   g_y);
    cudaGetSymbolAddress((void**)&ATT, g_att);
    cudaGetSymbolAddress((void**)&MLP, g_mlp);

    embed_kernel<<<MM, 256>>>(tok_emb, cls_emb, pos_emb, idx_tok, idx_cls, X);

    dim3 gridProj(CC / 128, (MM + 127) / 128);
    dim3 gridMlp1(C4 / 128, (MM + 127) / 128);
    dim3 gridMlp2(CC / 128, (MM + 127) / 128);
    dim3 gridLogit(VV / 128, (MM + 127) / 128);
    dim3 gridScore(9, 9, BB * NHH);
    dim3 gridAV(9, 2, BB * NHH);
    int smRows = (BB * NHH * TT + 3) / 4;

    for (int l = 0; l < LL; l++) {
        const float* l1w = ln1_w + (size_t)l * CC;
        const float* l1b = ln1_b + (size_t)l * CC;
        const float* wq  = Wq + (size_t)l * CC * CC;
        const float* wk  = Wk + (size_t)l * CC * CC;
        const float* wv  = Wv + (size_t)l * CC * CC;
        const float* wo  = Wo + (size_t)l * CC * CC;
        const float* bql = bq + (size_t)l * CC;
        const float* bkl = bk + (size_t)l * CC;
        const float* bvl = bv + (size_t)l * CC;
        const float* bol = bo + (size_t)l * CC;
        const float* l2w = ln2_w + (size_t)l * CC;
        const float* l2b = ln2_b + (size_t)l * CC;
        const float* w1  = W1 + (size_t)l * C4 * CC;
        const float* b1l = b1 + (size_t)l * C4;
        const float* w2  = W2 + (size_t)l * CC * C4;
        const float* b2l = b2 + (size_t)l * CC;

        layernorm_kernel<<<MM, 256>>>(X, l1w, l1b, H);

        tgemm_nt<false, false><<<gridProj, 256>>>(H, wq, bql, nullptr, Q, MM, CC, CC);
        tgemm_nt<false, false><<<gridProj, 256>>>(H, wk, bkl, nullptr, K, MM, CC, CC);
        tgemm_nt<false, false><<<gridProj, 256>>>(H, wv, bvl, nullptr, V, MM, CC, CC);

        attn_scores_kernel<<<gridScore, 256>>>(Q, K, ATT);
        softmax_kernel<<<smRows, 128>>>(ATT);
        attn_av_kernel<<<gridAV, 256>>>(ATT, V, Y);

        tgemm_nt<true, false><<<gridProj, 256>>>(Y, wo, bol, X, X, MM, CC, CC);

        layernorm_kernel<<<MM, 256>>>(X, l2w, l2b, H);
        tgemm_nt<false, true><<<gridMlp1, 256>>>(H, w1, b1l, nullptr, MLP, MM, C4, CC);
        tgemm_nt<true, false><<<gridMlp2, 256>>>(MLP, w2, b2l, X, X, MM, CC, C4);
    }

    layernorm_kernel<<<MM, 256>>>(X, lnf_w, lnf_b, H);
    tgemm_nt<false, false><<<gridLogit, 256>>>(H, tok_emb, nullptr, nullptr, out, MM, VV, CC);
}

// round 13
// speedup vs baseline: 1.2397x; 1.2397x over previous
#include <cuda_runtime.h>
#include <math.h>
#include <stdint.h>

// ---------------- problem constants ----------------
#define BB    32
#define TTOK  256
#define TT    257
#define CC    1024
#define NHH   16
#define HDD   64
#define LL    12
#define VV    16384
#define MM    (BB * TT)      // 8224
#define C4    (4 * CC)       // 4096
#define LN_EPS 1e-5f
#define ATT_SCALE 0.125f

// ---------------- scratch (device globals; no allocation allowed) ----------------
__device__ float g_x  [(size_t)MM * CC];
__device__ float g_h  [(size_t)MM * CC];
__device__ float g_q  [(size_t)MM * CC];
__device__ float g_k  [(size_t)MM * CC];
__device__ float g_v  [(size_t)MM * CC];
__device__ float g_y  [(size_t)MM * CC];
__device__ float g_att[(size_t)BB * NHH * TT * TT];
__device__ float g_mlp[(size_t)MM * C4];
// tf32-pre-rounded weight copies
__device__ float g_rwq[(size_t)LL * CC * CC];
__device__ float g_rwk[(size_t)LL * CC * CC];
__device__ float g_rwv[(size_t)LL * CC * CC];
__device__ float g_rwo[(size_t)LL * CC * CC];
__device__ float g_rw1[(size_t)LL * C4 * CC];
__device__ float g_rw2[(size_t)LL * CC * C4];
__device__ float g_remb[(size_t)VV * CC];

// ---------------- helpers ----------------
__device__ __forceinline__ uint32_t f2tf32(float f) {
    uint32_t u;
    asm("cvt.rna.tf32.f32 %0, %1;" : "=r"(u) : "f"(f));
    return u;
}
__device__ __forceinline__ float roundtf(float f) { return __uint_as_float(f2tf32(f)); }

__device__ __forceinline__ uint32_t smem_u32(const void* p) {
    uint32_t a;
    asm("{ .reg .u64 t; cvta.to.shared.u64 t, %1; cvt.u32.u64 %0, t; }" : "=r"(a) : "l"(p));
    return a;
}

__device__ __forceinline__ void mma_tf32(float* c, const uint32_t* a,
                                         uint32_t b0, uint32_t b1) {
    asm volatile(
        "mma.sync.aligned.m16n8k8.row.col.f32.tf32.tf32.f32 "
        "{%0,%1,%2,%3}, {%4,%5,%6,%7}, {%8,%9}, {%0,%1,%2,%3};\n"
        : "+f"(c[0]), "+f"(c[1]), "+f"(c[2]), "+f"(c[3])
        : "r"(a[0]), "r"(a[1]), "r"(a[2]), "r"(a[3]), "r"(b0), "r"(b1));
}

#define LDSM4(d, a) \
    asm volatile("ldmatrix.sync.aligned.m8n8.x4.shared.b16 {%0,%1,%2,%3}, [%4];" \
        : "=r"((d).x), "=r"((d).y), "=r"((d).z), "=r"((d).w) : "r"(a))

__device__ __forceinline__ void cp16(uint32_t dst, const void* src, uint32_t srcbytes) {
    asm volatile("cp.async.cg.shared.global [%0], [%1], 16, %2;\n"
                 :: "r"(dst), "l"(src), "r"(srcbytes) : "memory");
}
#define CP_COMMIT() asm volatile("cp.async.commit_group;\n" ::: "memory")
#define CP_WAIT(n)  asm volatile("cp.async.wait_group %0;\n" :: "n"(n) : "memory")

// ---------------- TF32 GEMM v4: cp.async + ldmatrix ----------------
// C = epi(A @ W^T + bias). Inputs tf32-pre-rounded fp32. Block 128x128, BK=16,
// 256 thr (8 warps 4m x 2n, warp tile 32x64). SMEM: K-major rows of 16B units,
// unit (row,kq) at row*64 + ((kq ^ ((row>>1)&3))*16); A at +0, B at +8192;
// 3 buffers x 16KB, distance-2 cp.async pipeline, one barrier per slab.
#define SLAB_BYTES 16384
template <bool RES, bool GELU_>
__global__ void __launch_bounds__(256, 2) tgemm_nt(
    const float* __restrict__ A, const float* __restrict__ W,
    const float* __restrict__ bias, const float* __restrict__ res,
    float* __restrict__ C, int M, int N, int K)
{
    extern __shared__ char smem[];
    uint32_t sb = smem_u32(smem);
    int tid = threadIdx.x, lane = tid & 31, wid = tid >> 5;
    int g = lane >> 2, t4 = lane & 3;
    int wm = (wid & 3) * 32, wn = (wid >> 2) * 64;
    int bm = blockIdx.y * 128, bn = blockIdx.x * 128;

    // ---- loader mapping: 2 x 16B units per matrix per thread ----
    int u0 = tid * 2;                 // even
    int lrow = u0 >> 2, kq0 = u0 & 3; // kq0 in {0,2}
    int swl = (lrow >> 1) & 3;
    uint32_t aD0 = lrow * 64 + ((kq0 ^ swl) * 16);
    uint32_t aD1 = lrow * 64 + (((kq0 + 1) ^ swl) * 16);
    bool aok = (bm + lrow) < M;
    const float* aSrc = A + (size_t)(aok ? bm + lrow : 0) * K + kq0 * 4;
    const float* bSrc = W + (size_t)(bn + lrow) * K + kq0 * 4;

    // ---- consumer LDSM address tables ----
    int Lr = lane & 7, Lb3 = (lane >> 3) & 1, Lb4 = (lane >> 4) & 1;
    uint32_t aAddr[2][2], bAddr[4][2];
    #pragma unroll
    for (int im = 0; im < 2; im++)
        #pragma unroll
        for (int ks = 0; ks < 2; ks++) {
            int r = wm + im * 16 + Lb3 * 8 + Lr;
            int kq = 2 * ks + Lb4;
            aAddr[im][ks] = r * 64 + ((kq ^ ((r >> 1) & 3)) * 16);
        }
    #pragma unroll
    for (int p = 0; p < 4; p++)
        #pragma unroll
        for (int ks = 0; ks < 2; ks++) {
            int r = wn + p * 16 + Lb4 * 8 + Lr;
            int kq = 2 * ks + Lb3;
            bAddr[p][ks] = 8192u + r * 64 + ((kq ^ ((r >> 1) & 3)) * 16);
        }

    float acc[2][8][4];
    #pragma unroll
    for (int im = 0; im < 2; im++)
        #pragma unroll
        for (int in_ = 0; in_ < 8; in_++)
            #pragma unroll
            for (int r = 0; r < 4; r++) acc[im][in_][r] = 0.f;

#define LOAD_SLAB(i, buf) {                                             \
        uint32_t _b = sb + (buf) * SLAB_BYTES;                          \
        int _k0 = (i) * 16;                                             \
        cp16(_b + aD0,         aSrc + _k0,     aok ? 16u : 0u);         \
        cp16(_b + aD1,         aSrc + _k0 + 4, aok ? 16u : 0u);         \
        cp16(_b + 8192u + aD0, bSrc + _k0,     16u);                    \
        cp16(_b + 8192u + aD1, bSrc + _k0 + 4, 16u);                    \
        CP_COMMIT(); }

    int ns = K / 16;
    LOAD_SLAB(0, 0);
    LOAD_SLAB(1, 1);

    for (int i = 0; i < ns; i++) {
        if (i + 1 < ns) CP_WAIT(1); else CP_WAIT(0);
        __syncthreads();
        if (i + 2 < ns) LOAD_SLAB(i + 2, (i + 2) % 3);
        uint32_t base = sb + (i % 3) * SLAB_BYTES;
        #pragma unroll
        for (int ks = 0; ks < 2; ks++) {
            uint4 af[2], bf[4];
            LDSM4(af[0], base + aAddr[0][ks]);
            LDSM4(af[1], base + aAddr[1][ks]);
            #pragma unroll
            for (int p = 0; p < 4; p++) LDSM4(bf[p], base + bAddr[p][ks]);
            #pragma unroll
            for (int p = 0; p < 4; p++) {
                mma_tf32(acc[0][2*p+0], (const uint32_t*)&af[0], bf[p].x, bf[p].y);
                mma_tf32(acc[1][2*p+0], (const uint32_t*)&af[1], bf[p].x, bf[p].y);
                mma_tf32(acc[0][2*p+1], (const uint32_t*)&af[0], bf[p].z, bf[p].w);
                mma_tf32(acc[1][2*p+1], (const uint32_t*)&af[1], bf[p].z, bf[p].w);
            }
        }
    }
#undef LOAD_SLAB

    // ---- epilogue ----
    #pragma unroll
    for (int im = 0; im < 2; im++) {
        int r0 = bm + wm + im * 16 + g;
        #pragma unroll
        for (int in_ = 0; in_ < 8; in_++) {
            int col = bn + wn + in_ * 8 + t4 * 2;
            float bx = 0.f, by = 0.f;
            if (bias) { bx = bias[col]; by = bias[col + 1]; }
            #pragma unroll
            for (int half = 0; half < 2; half++) {
                int row = r0 + half * 8;
                if (row >= M) continue;
                float vx = acc[im][in_][half * 2 + 0] + bx;
                float vy = acc[im][in_][half * 2 + 1] + by;
                if (GELU_) {
                    vx = roundtf(0.5f * vx * (1.f + erff(vx * 0.70710678118f)));
                    vy = roundtf(0.5f * vy * (1.f + erff(vy * 0.70710678118f)));
                }
                if (RES) {
                    float2 rv = *(const float2*)&res[(size_t)row * N + col];
                    vx += rv.x; vy += rv.y;
                }
                *(float2*)&C[(size_t)row * N + col] = make_float2(vx, vy);
            }
        }
    }
}

// ---------------- tf32 rounding copy (weights) ----------------
__global__ void __launch_bounds__(256) round_tf32_kernel(
    const float* __restrict__ src, float* __restrict__ dst, long n4)
{
    long idx = (long)blockIdx.x * blockDim.x + threadIdx.x;
    if (idx >= n4) return;
    float4 v = ((const float4*)src)[idx];
    v.x = roundtf(v.x); v.y = roundtf(v.y); v.z = roundtf(v.z); v.w = roundtf(v.w);
    ((float4*)dst)[idx] = v;
}

// ---------------- embedding ----------------
__global__ void __launch_bounds__(256) embed_kernel(
    const float* __restrict__ tok_emb, const float* __restrict__ cls_emb,
    const float* __restrict__ pos_emb, const int* __restrict__ idx_tok,
    const int* __restrict__ idx_cls, float* __restrict__ x)
{
    int bt = blockIdx.x;
    int b = bt / TT, t = bt % TT;
    const float* src;
    if (t == 0) src = cls_emb + (size_t)idx_cls[b] * CC;
    else        src = tok_emb + (size_t)idx_tok[b * TTOK + (t - 1)] * CC;
    const float4* s4 = (const float4*)src;
    const float4* p4 = (const float4*)(pos_emb + (size_t)t * CC);
    float4*       o4 = (float4*)(x + (size_t)bt * CC);
    int tid = threadIdx.x;
    float4 a = s4[tid], p = p4[tid];
    a.x += p.x; a.y += p.y; a.z += p.z; a.w += p.w;
    o4[tid] = a;
}

// ---------------- LayerNorm (output tf32-rounded; feeds GEMMs only) ----------------
__global__ void __launch_bounds__(256) layernorm_kernel(
    const float* __restrict__ x, const float* __restrict__ w,
    const float* __restrict__ b, float* __restrict__ out)
{
    int row = blockIdx.x;
    int tid = threadIdx.x;
    const float4* x4 = (const float4*)(x + (size_t)row * CC);
    float4 v = x4[tid];
    float s  = v.x + v.y + v.z + v.w;
    float ss = v.x * v.x + v.y * v.y + v.z * v.z + v.w * v.w;
    #pragma unroll
    for (int o = 16; o > 0; o >>= 1) {
        s  += __shfl_xor_sync(0xffffffffu, s,  o);
        ss += __shfl_xor_sync(0xffffffffu, ss, o);
    }
    __shared__ float rs[8], rss[8], bc[2];
    int wid = tid >> 5, lane = tid & 31;
    if (lane == 0) { rs[wid] = s; rss[wid] = ss; }
    __syncthreads();
    if (wid == 0) {
        float a  = (lane < 8) ? rs[lane]  : 0.f;
        float a2 = (lane < 8) ? rss[lane] : 0.f;
        #pragma unroll
        for (int o = 4; o > 0; o >>= 1) {
            a  += __shfl_xor_sync(0xffffffffu, a,  o);
            a2 += __shfl_xor_sync(0xffffffffu, a2, o);
        }
        if (lane == 0) { bc[0] = a; bc[1] = a2; }
    }
    __syncthreads();
    float mean = bc[0] * (1.0f / CC);
    float var  = bc[1] * (1.0f / CC) - mean * mean;
    float inv  = rsqrtf(var + LN_EPS);
    const float4* w4 = (const float4*)w;
    const float4* b4 = (const float4*)b;
    float4 wv = w4[tid], bv = b4[tid], o;
    o.x = roundtf((v.x - mean) * inv * wv.x + bv.x);
    o.y = roundtf((v.y - mean) * inv * wv.y + bv.y);
    o.z = roundtf((v.z - mean) * inv * wv.z + bv.z);
    o.w = roundtf((v.w - mean) * inv * wv.w + bv.w);
    ((float4*)(out + (size_t)row * CC))[tid] = o;
}

// ---------------- attention scores (fp32) ----------------
__global__ void __launch_bounds__(256) attn_scores_kernel(
    const float* __restrict__ q, const float* __restrict__ k, float* __restrict__ att)
{
    int jt = blockIdx.x, it = blockIdx.y;
    if (jt > it) return;
    int bh = blockIdx.z;
    int b = bh / NHH, h = bh % NHH;
    __shared__ float Qs[32][65];
    __shared__ float Ks[32][65];
    int tid = threadIdx.x;

    #pragma unroll
    for (int rep = 0; rep < 2; rep++) {
        int f = tid + rep * 256;
        int row = f >> 4;
        int c4  = (f & 15) * 4;
        {
            int i = it * 32 + row;
            float4 v = make_float4(0.f, 0.f, 0.f, 0.f);
            if (i < TT) v = *(const float4*)&q[(((size_t)b * TT + i) * NHH + h) * HDD + c4];
            Qs[row][c4+0]=v.x; Qs[row][c4+1]=v.y; Qs[row][c4+2]=v.z; Qs[row][c4+3]=v.w;
        }
        {
            int j = jt * 32 + row;
            float4 v = make_float4(0.f, 0.f, 0.f, 0.f);
            if (j < TT) v = *(const float4*)&k[(((size_t)b * TT + j) * NHH + h) * HDD + c4];
            Ks[row][c4+0]=v.x; Ks[row][c4+1]=v.y; Ks[row][c4+2]=v.z; Ks[row][c4+3]=v.w;
        }
    }
    __syncthreads();

    int il = tid >> 3;
    int jb = (tid & 7) * 4;
    float a0 = 0.f, a1 = 0.f, a2 = 0.f, a3 = 0.f;
    #pragma unroll
    for (int kk = 0; kk < 64; kk++) {
        float qv = Qs[il][kk];
        a0 = fmaf(qv, Ks[jb + 0][kk], a0);
        a1 = fmaf(qv, Ks[jb + 1][kk], a1);
        a2 = fmaf(qv, Ks[jb + 2][kk], a2);
        a3 = fmaf(qv, Ks[jb + 3][kk], a3);
    }
    int i = it * 32 + il;
    if (i < TT) {
        size_t base = ((size_t)bh * TT + i) * TT;
        float r[4] = {a0, a1, a2, a3};
        #pragma unroll
        for (int u = 0; u < 4; u++) {
            int j = jt * 32 + jb + u;
            if (j < TT && j <= i) att[base + j] = r[u] * ATT_SCALE;
        }
    }
}

// ---------------- causal softmax ----------------
__global__ void __launch_bounds__(128) softmax_kernel(float* __restrict__ att)
{
    int row = blockIdx.x * 4 + (threadIdx.x >> 5);
    if (row >= BB * NHH * TT) return;
    int lane = threadIdx.x & 31;
    int i = row % TT;
    float* p = att + (size_t)row * TT;
    int len = i + 1;
    float m = -3.4e38f;
    for (int j = lane; j < len; j += 32) m = fmaxf(m, p[j]);
    #pragma unroll
    for (int o = 16; o > 0; o >>= 1) m = fmaxf(m, __shfl_xor_sync(0xffffffffu, m, o));
    float s = 0.f;
    for (int j = lane; j < len; j += 32) { float e = expf(p[j] - m); p[j] = e; s += e; }
    #pragma unroll
    for (int o = 16; o > 0; o >>= 1) s += __shfl_xor_sync(0xffffffffu, s, o);
    float inv = 1.f / s;
    for (int j = lane; j < TT; j += 32) p[j] = (j < len) ? p[j] * inv : 0.f;
}

// ---------------- AV (fp32; output tf32-rounded: feeds Wo GEMM only) ----------------
__global__ void __launch_bounds__(256) attn_av_kernel(
    const float* __restrict__ att, const float* __restrict__ v, float* __restrict__ y)
{
    int it = blockIdx.x, dt = blockIdx.y, bh = blockIdx.z;
    int b = bh / NHH, h = bh % NHH;
    __shared__ float As[32][33];
    __shared__ float Vs[32][33];
    int tid = threadIdx.x;
    int il = tid >> 3;
    int db = (tid & 7) * 4;
    float acc0 = 0.f, acc1 = 0.f, acc2 = 0.f, acc3 = 0.f;

    for (int j0 = 0; j0 < TT; j0 += 32) {
        {
            int r  = tid >> 3;
            int cb = (tid & 7) * 4;
            int i  = it * 32 + r;
            #pragma unroll
            for (int u = 0; u < 4; u++) {
                int j = j0 + cb + u;
                As[r][cb + u] = (i < TT && j < TT) ? att[((size_t)bh * TT + i) * TT + j] : 0.f;
            }
            int jr = j0 + r;
            float4 vv = make_float4(0.f, 0.f, 0.f, 0.f);
            if (jr < TT)
                vv = *(const float4*)&v[(((size_t)b * TT + jr) * NHH + h) * HDD + dt * 32 + cb];
            Vs[r][cb+0]=vv.x; Vs[r][cb+1]=vv.y; Vs[r][cb+2]=vv.z; Vs[r][cb+3]=vv.w;
        }
        __syncthreads();
        #pragma unroll
        for (int jj = 0; jj < 32; jj++) {
            float a = As[il][jj];
            acc0 = fmaf(a, Vs[jj][db + 0], acc0);
            acc1 = fmaf(a, Vs[jj][db + 1], acc1);
            acc2 = fmaf(a, Vs[jj][db + 2], acc2);
            acc3 = fmaf(a, Vs[jj][db + 3], acc3);
        }
        __syncthreads();
    }
    int i = it * 32 + il;
    if (i < TT) {
        size_t base = (((size_t)b * TT + i) * NHH + h) * HDD + dt * 32 + db;
        float4 o = make_float4(roundtf(acc0), roundtf(acc1), roundtf(acc2), roundtf(acc3));
        *(float4*)&y[base] = o;
    }
}

// ---------------- host orchestration ----------------
extern "C" void kernel_launch(void* const* d_in, const int* in_sizes, int n_in,
                              void* d_out, int out_size)
{
    const float* tok_emb = (const float*)d_in[0];
    const float* cls_emb = (const float*)d_in[1];
    const float* pos_emb = (const float*)d_in[2];
    const float* ln1_w   = (const float*)d_in[3];
    const float* ln1_b   = (const float*)d_in[4];
    const float* Wq      = (const float*)d_in[5];
    const float* bq      = (const float*)d_in[6];
    const float* Wk      = (const float*)d_in[7];
    const float* bk      = (const float*)d_in[8];
    const float* Wv      = (const float*)d_in[9];
    const float* bv      = (const float*)d_in[10];
    const float* Wo      = (const float*)d_in[11];
    const float* bo      = (const float*)d_in[12];
    const float* ln2_w   = (const float*)d_in[13];
    const float* ln2_b   = (const float*)d_in[14];
    const float* W1      = (const float*)d_in[15];
    const float* b1      = (const float*)d_in[16];
    const float* W2      = (const float*)d_in[17];
    const float* b2      = (const float*)d_in[18];
    const float* lnf_w   = (const float*)d_in[19];
    const float* lnf_b   = (const float*)d_in[20];
    const int* idx_tok   = (const int*)d_in[21];
    const int* idx_cls   = (const int*)d_in[22];
    float* out = (float*)d_out;

    float *X, *H, *Q, *K, *V, *Y, *ATT, *MLP;
    float *RWQ, *RWK, *RWV, *RWO, *RW1, *RW2, *REMB;
    cudaGetSymbolAddress((void**)&X,   g_x);
    cudaGetSymbolAddress((void**)&H,   g_h);
    cudaGetSymbolAddress((void**)&Q,   g_q);
    cudaGetSymbolAddress((void**)&K,   g_k);
    cudaGetSymbolAddress((void**)&V,   g_v);
    cudaGetSymbolAddress((void**)&Y,   g_y);
    cudaGetSymbolAddress((void**)&ATT, g_att);
    cudaGetSymbolAddress((void**)&MLP, g_mlp);
    cudaGetSymbolAddress((void**)&RWQ, g_rwq);
    cudaGetSymbolAddress((void**)&RWK, g_rwk);
    cudaGetSymbolAddress((void**)&RWV, g_rwv);
    cudaGetSymbolAddress((void**)&RWO, g_rwo);
    cudaGetSymbolAddress((void**)&RW1, g_rw1);
    cudaGetSymbolAddress((void**)&RW2, g_rw2);
    cudaGetSymbolAddress((void**)&REMB, g_remb);

    // pre-round weights to tf32 grid (identical cvt.rna values as R6's in-loader cvt)
    {
        long nqk = (long)LL * CC * CC / 4;
        long nm  = (long)LL * C4 * CC / 4;
        long ne  = (long)VV * CC / 4;
        round_tf32_kernel<<<(unsigned)((nqk + 255) / 256), 256>>>(Wq, RWQ, nqk);
        round_tf32_kernel<<<(unsigned)((nqk + 255) / 256), 256>>>(Wk, RWK, nqk);
        round_tf32_kernel<<<(unsigned)((nqk + 255) / 256), 256>>>(Wv, RWV, nqk);
        round_tf32_kernel<<<(unsigned)((nqk + 255) / 256), 256>>>(Wo, RWO, nqk);
        round_tf32_kernel<<<(unsigned)((nm + 255) / 256), 256>>>(W1, RW1, nm);
        round_tf32_kernel<<<(unsigned)((nm + 255) / 256), 256>>>(W2, RW2, nm);
        round_tf32_kernel<<<(unsigned)((ne + 255) / 256), 256>>>(tok_emb, REMB, ne);
    }

    embed_kernel<<<MM, 256>>>(tok_emb, cls_emb, pos_emb, idx_tok, idx_cls, X);

    const int SM_DYN = 3 * SLAB_BYTES;   // 49152 (== default dyn-smem limit)
    dim3 gProj(CC / 128, (MM + 127) / 128);      // (8, 65)
    dim3 gMlp1(C4 / 128, (MM + 127) / 128);      // (32, 65)
    dim3 gMlp2(CC / 128, (MM + 127) / 128);
    dim3 gLogit(VV / 128, (MM + 127) / 128);     // (128, 65)
    dim3 gridScore(9, 9, BB * NHH);
    dim3 gridAV(9, 2, BB * NHH);
    int smRows = (BB * NHH * TT + 3) / 4;

    for (int l = 0; l < LL; l++) {
        const float* l1w = ln1_w + (size_t)l * CC;
        const float* l1b = ln1_b + (size_t)l * CC;
        const float* rwq = RWQ + (size_t)l * CC * CC;
        const float* rwk = RWK + (size_t)l * CC * CC;
        const float* rwv = RWV + (size_t)l * CC * CC;
        const float* rwo = RWO + (size_t)l * CC * CC;
        const float* bql = bq + (size_t)l * CC;
        const float* bkl = bk + (size_t)l * CC;
        const float* bvl = bv + (size_t)l * CC;
        const float* bol = bo + (size_t)l * CC;
        const float* l2w = ln2_w + (size_t)l * CC;
        const float* l2b = ln2_b + (size_t)l * CC;
        const float* rw1 = RW1 + (size_t)l * C4 * CC;
        const float* b1l = b1 + (size_t)l * C4;
        const float* rw2 = RW2 + (size_t)l * CC * C4;
        const float* b2l = b2 + (size_t)l * CC;

        layernorm_kernel<<<MM, 256>>>(X, l1w, l1b, H);

        tgemm_nt<false,false><<<gProj, 256, SM_DYN>>>(H, rwq, bql, nullptr, Q, MM, CC, CC);
        tgemm_nt<false,false><<<gProj, 256, SM_DYN>>>(H, rwk, bkl, nullptr, K, MM, CC, CC);
        tgemm_nt<false,false><<<gProj, 256, SM_DYN>>>(H, rwv, bvl, nullptr, V, MM, CC, CC);

        attn_scores_kernel<<<gridScore, 256>>>(Q, K, ATT);
        softmax_kernel<<<smRows, 128>>>(ATT);
        attn_av_kernel<<<gridAV, 256>>>(ATT, V, Y);

        tgemm_nt<true,false><<<gProj, 256, SM_DYN>>>(Y, rwo, bol, X, X, MM, CC, CC);

        layernorm_kernel<<<MM, 256>>>(X, l2w, l2b, H);
        tgemm_nt<false,true><<<gMlp1, 256, SM_DYN>>>(H, rw1, b1l, nullptr, MLP, MM, C4, CC);
        tgemm_nt<true,false><<<gMlp2, 256, SM_DYN>>>(MLP, rw2, b2l, X, X, MM, CC, C4);
    }

    layernorm_kernel<<<MM, 256>>>(X, lnf_w, lnf_b, H);
    tgemm_nt<false,false><<<gLogit, 256, SM_DYN>>>(H, REMB, nullptr, nullptr, out, MM, VV, CC);
}

// round 16
// speedup vs baseline: 1.3142x; 1.0602x over previous
#include <cuda_runtime.h>
#include <math.h>
#include <stdint.h>

// ---------------- problem constants ----------------
#define BB    32
#define TTOK  256
#define TT    257
#define CC    1024
#define NHH   16
#define HDD   64
#define LL    12
#define VV    16384
#define MM    (BB * TT)      // 8224
#define C4    (4 * CC)       // 4096
#define QKVS  (3 * CC)       // 3072
#define LN_EPS 1e-5f
#define ATT_SCALE 0.125f

// ---------------- scratch (device globals; no allocation allowed) ----------------
__device__ float g_x   [(size_t)MM * CC];
__device__ float g_h   [(size_t)MM * CC];
__device__ float g_qkv [(size_t)MM * QKVS];
__device__ float g_y   [(size_t)MM * CC];
__device__ float g_mlp [(size_t)MM * C4];
// tf32-pre-rounded weights
__device__ float g_rwqkv[(size_t)LL * QKVS * CC];
__device__ float g_bqkv [(size_t)LL * QKVS];
__device__ float g_rwo  [(size_t)LL * CC * CC];
__device__ float g_rw1  [(size_t)LL * C4 * CC];
__device__ float g_rw2  [(size_t)LL * CC * C4];
__device__ float g_remb [(size_t)VV * CC];

// ---------------- helpers ----------------
__device__ __forceinline__ uint32_t f2tf32(float f) {
    uint32_t u;
    asm("cvt.rna.tf32.f32 %0, %1;" : "=r"(u) : "f"(f));
    return u;
}
__device__ __forceinline__ float roundtf(float f) { return __uint_as_float(f2tf32(f)); }

__device__ __forceinline__ uint32_t smem_u32(const void* p) {
    uint32_t a;
    asm("{ .reg .u64 t; cvta.to.shared.u64 t, %1; cvt.u32.u64 %0, t; }" : "=r"(a) : "l"(p));
    return a;
}

__device__ __forceinline__ void mma_tf32(float* c, const uint32_t* a,
                                         uint32_t b0, uint32_t b1) {
    asm volatile(
        "mma.sync.aligned.m16n8k8.row.col.f32.tf32.tf32.f32 "
        "{%0,%1,%2,%3}, {%4,%5,%6,%7}, {%8,%9}, {%0,%1,%2,%3};\n"
        : "+f"(c[0]), "+f"(c[1]), "+f"(c[2]), "+f"(c[3])
        : "r"(a[0]), "r"(a[1]), "r"(a[2]), "r"(a[3]), "r"(b0), "r"(b1));
}

#define LDSM4(d, a) \
    asm volatile("ldmatrix.sync.aligned.m8n8.x4.shared.b16 {%0,%1,%2,%3}, [%4];" \
        : "=r"((d).x), "=r"((d).y), "=r"((d).z), "=r"((d).w) : "r"(a))

__device__ __forceinline__ void cp16(uint32_t dst, const void* src, uint32_t srcbytes) {
    asm volatile("cp.async.cg.shared.global [%0], [%1], 16, %2;\n"
                 :: "r"(dst), "l"(src), "r"(srcbytes) : "memory");
}
#define CP_COMMIT() asm volatile("cp.async.commit_group;\n" ::: "memory")
#define CP_WAIT(n)  asm volatile("cp.async.wait_group %0;\n" :: "n"(n) : "memory")

// ---------------- TF32 GEMM: cp.async + ldmatrix (R13 winner, unchanged) ------
#define SLAB_BYTES 16384
template <bool RES, bool GELU_>
__global__ void __launch_bounds__(256, 2) tgemm_nt(
    const float* __restrict__ A, const float* __restrict__ W,
    const float* __restrict__ bias, const float* __restrict__ res,
    float* __restrict__ C, int M, int N, int K)
{
    extern __shared__ char smem[];
    uint32_t sb = smem_u32(smem);
    int tid = threadIdx.x, lane = tid & 31, wid = tid >> 5;
    int g = lane >> 2, t4 = lane & 3;
    int wm = (wid & 3) * 32, wn = (wid >> 2) * 64;
    int bm = blockIdx.y * 128, bn = blockIdx.x * 128;

    int u0 = tid * 2;
    int lrow = u0 >> 2, kq0 = u0 & 3;
    int swl = (lrow >> 1) & 3;
    uint32_t aD0 = lrow * 64 + ((kq0 ^ swl) * 16);
    uint32_t aD1 = lrow * 64 + (((kq0 + 1) ^ swl) * 16);
    bool aok = (bm + lrow) < M;
    const float* aSrc = A + (size_t)(aok ? bm + lrow : 0) * K + kq0 * 4;
    const float* bSrc = W + (size_t)(bn + lrow) * K + kq0 * 4;

    int Lr = lane & 7, Lb3 = (lane >> 3) & 1, Lb4 = (lane >> 4) & 1;
    uint32_t aAddr[2][2], bAddr[4][2];
    #pragma unroll
    for (int im = 0; im < 2; im++)
        #pragma unroll
        for (int ks = 0; ks < 2; ks++) {
            int r = wm + im * 16 + Lb3 * 8 + Lr;
            int kq = 2 * ks + Lb4;
            aAddr[im][ks] = r * 64 + ((kq ^ ((r >> 1) & 3)) * 16);
        }
    #pragma unroll
    for (int p = 0; p < 4; p++)
        #pragma unroll
        for (int ks = 0; ks < 2; ks++) {
            int r = wn + p * 16 + Lb4 * 8 + Lr;
            int kq = 2 * ks + Lb3;
            bAddr[p][ks] = 8192u + r * 64 + ((kq ^ ((r >> 1) & 3)) * 16);
        }

    float acc[2][8][4];
    #pragma unroll
    for (int im = 0; im < 2; im++)
        #pragma unroll
        for (int in_ = 0; in_ < 8; in_++)
            #pragma unroll
            for (int r = 0; r < 4; r++) acc[im][in_][r] = 0.f;

#define LOAD_SLAB(i, buf) {                                             \
        uint32_t _b = sb + (buf) * SLAB_BYTES;                          \
        int _k0 = (i) * 16;                                             \
        cp16(_b + aD0,         aSrc + _k0,     aok ? 16u : 0u);         \
        cp16(_b + aD1,         aSrc + _k0 + 4, aok ? 16u : 0u);         \
        cp16(_b + 8192u + aD0, bSrc + _k0,     16u);                    \
        cp16(_b + 8192u + aD1, bSrc + _k0 + 4, 16u);                    \
        CP_COMMIT(); }

    int ns = K / 16;
    LOAD_SLAB(0, 0);
    LOAD_SLAB(1, 1);

    for (int i = 0; i < ns; i++) {
        if (i + 1 < ns) CP_WAIT(1); else CP_WAIT(0);
        __syncthreads();
        if (i + 2 < ns) LOAD_SLAB(i + 2, (i + 2) % 3);
        uint32_t base = sb + (i % 3) * SLAB_BYTES;
        #pragma unroll
        for (int ks = 0; ks < 2; ks++) {
            uint4 af[2], bf[4];
            LDSM4(af[0], base + aAddr[0][ks]);
            LDSM4(af[1], base + aAddr[1][ks]);
            #pragma unroll
            for (int p = 0; p < 4; p++) LDSM4(bf[p], base + bAddr[p][ks]);
            #pragma unroll
            for (int p = 0; p < 4; p++) {
                mma_tf32(acc[0][2*p+0], (const uint32_t*)&af[0], bf[p].x, bf[p].y);
                mma_tf32(acc[1][2*p+0], (const uint32_t*)&af[1], bf[p].x, bf[p].y);
                mma_tf32(acc[0][2*p+1], (const uint32_t*)&af[0], bf[p].z, bf[p].w);
                mma_tf32(acc[1][2*p+1], (const uint32_t*)&af[1], bf[p].z, bf[p].w);
            }
        }
    }
#undef LOAD_SLAB

    #pragma unroll
    for (int im = 0; im < 2; im++) {
        int r0 = bm + wm + im * 16 + g;
        #pragma unroll
        for (int in_ = 0; in_ < 8; in_++) {
            int col = bn + wn + in_ * 8 + t4 * 2;
            float bx = 0.f, by = 0.f;
            if (bias) { bx = bias[col]; by = bias[col + 1]; }
            #pragma unroll
            for (int half = 0; half < 2; half++) {
                int row = r0 + half * 8;
                if (row >= M) continue;
                float vx = acc[im][in_][half * 2 + 0] + bx;
                float vy = acc[im][in_][half * 2 + 1] + by;
                if (GELU_) {
                    vx = roundtf(0.5f * vx * (1.f + erff(vx * 0.70710678118f)));
                    vy = roundtf(0.5f * vy * (1.f + erff(vy * 0.70710678118f)));
                }
                if (RES) {
                    float2 rv = *(const float2*)&res[(size_t)row * N + col];
                    vx += rv.x; vy += rv.y;
                }
                *(float2*)&C[(size_t)row * N + col] = make_float2(vx, vy);
            }
        }
    }
}

// ---------------- fused flash attention (replaces scores+softmax+AV) ----------------
// grid (9 q-tiles, BB*NHH). 32 q-rows per block; stream K/V in 32-row tiles with
// causal tile-skip; online softmax; output y tf32-rounded (as old AV did).
__global__ void __launch_bounds__(256) flash_attn_kernel(
    const float* __restrict__ qkv, float* __restrict__ y)
{
    int it = blockIdx.x, bh = blockIdx.y;
    int b = bh / NHH, h = bh % NHH;
    __shared__ float Qs[32][65];
    __shared__ float Ks[32][65];
    __shared__ float Vs[32][68];
    __shared__ float Ps[32][33];
    int tid = threadIdx.x;
    int il = tid >> 3;                 // q-row in tile
    int q8 = tid & 7;
    int jb = q8 * 4;

    // load Q tile
    #pragma unroll
    for (int rep = 0; rep < 2; rep++) {
        int f = tid + rep * 256;
        int row = f >> 4, c4 = (f & 15) * 4;
        int i = it * 32 + row;
        float4 v = make_float4(0.f, 0.f, 0.f, 0.f);
        if (i < TT) v = *(const float4*)&qkv[(size_t)(b * TT + i) * QKVS + h * HDD + c4];
        Qs[row][c4+0]=v.x; Qs[row][c4+1]=v.y; Qs[row][c4+2]=v.z; Qs[row][c4+3]=v.w;
    }
    __syncthreads();

    int i = it * 32 + il;
    float m = -3.0e38f, l = 0.f;
    float acc[8];
    #pragma unroll
    for (int d = 0; d < 8; d++) acc[d] = 0.f;

    for (int jt = 0; jt <= it; jt++) {
        int j0 = jt * 32;
        // load K and V tiles
        #pragma unroll
        for (int rep = 0; rep < 2; rep++) {
            int f = tid + rep * 256;
            int row = f >> 4, c4 = (f & 15) * 4;
            int j = j0 + row;
            float4 kv = make_float4(0.f, 0.f, 0.f, 0.f);
            float4 vv = make_float4(0.f, 0.f, 0.f, 0.f);
            if (j < TT) {
                size_t base = (size_t)(b * TT + j) * QKVS + h * HDD + c4;
                kv = *(const float4*)&qkv[base + CC];
                vv = *(const float4*)&qkv[base + 2 * CC];
            }
            Ks[row][c4+0]=kv.x; Ks[row][c4+1]=kv.y; Ks[row][c4+2]=kv.z; Ks[row][c4+3]=kv.w;
            *(float4*)&Vs[row][c4] = vv;
        }
        __syncthreads();

        // scores for this thread's 4 columns
        float s0 = 0.f, s1 = 0.f, s2 = 0.f, s3 = 0.f;
        #pragma unroll
        for (int kk = 0; kk < HDD; kk++) {
            float qv = Qs[il][kk];
            s0 = fmaf(qv, Ks[jb + 0][kk], s0);
            s1 = fmaf(qv, Ks[jb + 1][kk], s1);
            s2 = fmaf(qv, Ks[jb + 2][kk], s2);
            s3 = fmaf(qv, Ks[jb + 3][kk], s3);
        }
        float sv[4] = {s0 * ATT_SCALE, s1 * ATT_SCALE, s2 * ATT_SCALE, s3 * ATT_SCALE};
        #pragma unroll
        for (int u = 0; u < 4; u++)
            if (j0 + jb + u > i) sv[u] = -1.0e38f;

        float tmax = fmaxf(fmaxf(sv[0], sv[1]), fmaxf(sv[2], sv[3]));
        #pragma unroll
        for (int o = 1; o < 8; o <<= 1)
            tmax = fmaxf(tmax, __shfl_xor_sync(0xffffffffu, tmax, o));
        float newm = fmaxf(m, tmax);
        float corr = expf(m - newm);
        float p[4], psum = 0.f;
        #pragma unroll
        for (int u = 0; u < 4; u++) { p[u] = expf(sv[u] - newm); psum += p[u]; }
        #pragma unroll
        for (int o = 1; o < 8; o <<= 1)
            psum += __shfl_xor_sync(0xffffffffu, psum, o);
        l = l * corr + psum;
        m = newm;
        #pragma unroll
        for (int d = 0; d < 8; d++) acc[d] *= corr;
        #pragma unroll
        for (int u = 0; u < 4; u++) Ps[il][jb + u] = p[u];
        __syncwarp();

        // P @ V for this thread's 8 output dims
        #pragma unroll 8
        for (int j = 0; j < 32; j++) {
            float pj = Ps[il][j];
            float4 v0 = *(const float4*)&Vs[j][q8 * 8];
            float4 v1 = *(const float4*)&Vs[j][q8 * 8 + 4];
            acc[0] = fmaf(pj, v0.x, acc[0]); acc[1] = fmaf(pj, v0.y, acc[1]);
            acc[2] = fmaf(pj, v0.z, acc[2]); acc[3] = fmaf(pj, v0.w, acc[3]);
            acc[4] = fmaf(pj, v1.x, acc[4]); acc[5] = fmaf(pj, v1.y, acc[5]);
            acc[6] = fmaf(pj, v1.z, acc[6]); acc[7] = fmaf(pj, v1.w, acc[7]);
        }
        __syncthreads();
    }

    if (i < TT) {
        float inv = 1.f / l;
        float* dst = y + (size_t)(b * TT + i) * CC + h * HDD + q8 * 8;
        float4 o0, o1;
        o0.x = roundtf(acc[0] * inv); o0.y = roundtf(acc[1] * inv);
        o0.z = roundtf(acc[2] * inv); o0.w = roundtf(acc[3] * inv);
        o1.x = roundtf(acc[4] * inv); o1.y = roundtf(acc[5] * inv);
        o1.z = roundtf(acc[6] * inv); o1.w = roundtf(acc[7] * inv);
        *(float4*)dst = o0;
        *(float4*)(dst + 4) = o1;
    }
}

// ---------------- tf32 rounding copy ----------------
__global__ void __launch_bounds__(256) round_tf32_kernel(
    const float* __restrict__ src, float* __restrict__ dst, long n4)
{
    long idx = (long)blockIdx.x * blockDim.x + threadIdx.x;
    if (idx >= n4) return;
    float4 v = ((const float4*)src)[idx];
    v.x = roundtf(v.x); v.y = roundtf(v.y); v.z = roundtf(v.z); v.w = roundtf(v.w);
    ((float4*)dst)[idx] = v;
}

// ---------------- embedding ----------------
__global__ void __launch_bounds__(256) embed_kernel(
    const float* __restrict__ tok_emb, const float* __restrict__ cls_emb,
    const float* __restrict__ pos_emb, const int* __restrict__ idx_tok,
    const int* __restrict__ idx_cls, float* __restrict__ x)
{
    int bt = blockIdx.x;
    int b = bt / TT, t = bt % TT;
    const float* src;
    if (t == 0) src = cls_emb + (size_t)idx_cls[b] * CC;
    else        src = tok_emb + (size_t)idx_tok[b * TTOK + (t - 1)] * CC;
    const float4* s4 = (const float4*)src;
    const float4* p4 = (const float4*)(pos_emb + (size_t)t * CC);
    float4*       o4 = (float4*)(x + (size_t)bt * CC);
    int tid = threadIdx.x;
    float4 a = s4[tid], p = p4[tid];
    a.x += p.x; a.y += p.y; a.z += p.z; a.w += p.w;
    o4[tid] = a;
}

// ---------------- LayerNorm (output tf32-rounded; feeds GEMMs only) ----------------
__global__ void __launch_bounds__(256) layernorm_kernel(
    const float* __restrict__ x, const float* __restrict__ w,
    const float* __restrict__ b, float* __restrict__ out)
{
    int row = blockIdx.x;
    int tid = threadIdx.x;
    const float4* x4 = (const float4*)(x + (size_t)row * CC);
    float4 v = x4[tid];
    float s  = v.x + v.y + v.z + v.w;
    float ss = v.x * v.x + v.y * v.y + v.z * v.z + v.w * v.w;
    #pragma unroll
    for (int o = 16; o > 0; o >>= 1) {
        s  += __shfl_xor_sync(0xffffffffu, s,  o);
        ss += __shfl_xor_sync(0xffffffffu, ss, o);
    }
    __shared__ float rs[8], rss[8], bc[2];
    int wid = tid >> 5, lane = tid & 31;
    if (lane == 0) { rs[wid] = s; rss[wid] = ss; }
    __syncthreads();
    if (wid == 0) {
        float a  = (lane < 8) ? rs[lane]  : 0.f;
        float a2 = (lane < 8) ? rss[lane] : 0.f;
        #pragma unroll
        for (int o = 4; o > 0; o >>= 1) {
            a  += __shfl_xor_sync(0xffffffffu, a,  o);
            a2 += __shfl_xor_sync(0xffffffffu, a2, o);
        }
        if (lane == 0) { bc[0] = a; bc[1] = a2; }
    }
    __syncthreads();
    float mean = bc[0] * (1.0f / CC);
    float var  = bc[1] * (1.0f / CC) - mean * mean;
    float inv  = rsqrtf(var + LN_EPS);
    const float4* w4 = (const float4*)w;
    const float4* b4 = (const float4*)b;
    float4 wv = w4[tid], bv = b4[tid], o;
    o.x = roundtf((v.x - mean) * inv * wv.x + bv.x);
    o.y = roundtf((v.y - mean) * inv * wv.y + bv.y);
    o.z = roundtf((v.z - mean) * inv * wv.z + bv.z);
    o.w = roundtf((v.w - mean) * inv * wv.w + bv.w);
    ((float4*)(out + (size_t)row * CC))[tid] = o;
}

// ---------------- host orchestration ----------------
extern "C" void kernel_launch(void* const* d_in, const int* in_sizes, int n_in,
                              void* d_out, int out_size)
{
    const float* tok_emb = (const float*)d_in[0];
    const float* cls_emb = (const float*)d_in[1];
    const float* pos_emb = (const float*)d_in[2];
    const float* ln1_w   = (const float*)d_in[3];
    const float* ln1_b   = (const float*)d_in[4];
    const float* Wq      = (const float*)d_in[5];
    const float* bq      = (const float*)d_in[6];
    const float* Wk      = (const float*)d_in[7];
    const float* bk      = (const float*)d_in[8];
    const float* Wv      = (const float*)d_in[9];
    const float* bv      = (const float*)d_in[10];
    const float* Wo      = (const float*)d_in[11];
    const float* bo      = (const float*)d_in[12];
    const float* ln2_w   = (const float*)d_in[13];
    const float* ln2_b   = (const float*)d_in[14];
    const float* W1      = (const float*)d_in[15];
    const float* b1      = (const float*)d_in[16];
    const float* W2      = (const float*)d_in[17];
    const float* b2      = (const float*)d_in[18];
    const float* lnf_w   = (const float*)d_in[19];
    const float* lnf_b   = (const float*)d_in[20];
    const int* idx_tok   = (const int*)d_in[21];
    const int* idx_cls   = (const int*)d_in[22];
    float* out = (float*)d_out;

    float *X, *H, *QKV, *Y, *MLP;
    float *RWQKV, *BQKV, *RWO, *RW1, *RW2, *REMB;
    cudaGetSymbolAddress((void**)&X,    g_x);
    cudaGetSymbolAddress((void**)&H,    g_h);
    cudaGetSymbolAddress((void**)&QKV,  g_qkv);
    cudaGetSymbolAddress((void**)&Y,    g_y);
    cudaGetSymbolAddress((void**)&MLP,  g_mlp);
    cudaGetSymbolAddress((void**)&RWQKV, g_rwqkv);
    cudaGetSymbolAddress((void**)&BQKV,  g_bqkv);
    cudaGetSymbolAddress((void**)&RWO,  g_rwo);
    cudaGetSymbolAddress((void**)&RW1,  g_rw1);
    cudaGetSymbolAddress((void**)&RW2,  g_rw2);
    cudaGetSymbolAddress((void**)&REMB, g_remb);

    // ---- pack + tf32-round weights (identical cvt.rna values as before) ----
    {
        long n1 = (long)CC * CC / 4;          // one layer's Wq/Wk/Wv slab
        long nqk = (long)LL * CC * CC / 4;
        long nm  = (long)LL * C4 * CC / 4;
        long ne  = (long)VV * CC / 4;
        unsigned g1 = (unsigned)((n1 + 255) / 256);
        for (int l = 0; l < LL; l++) {
            float* base = RWQKV + (size_t)l * QKVS * CC;
            round_tf32_kernel<<<g1, 256>>>(Wq + (size_t)l * CC * CC, base,                        n1);
            round_tf32_kernel<<<g1, 256>>>(Wk + (size_t)l * CC * CC, base + (size_t)CC * CC,     n1);
            round_tf32_kernel<<<g1, 256>>>(Wv + (size_t)l * CC * CC, base + (size_t)2 * CC * CC, n1);
            cudaMemcpyAsync(BQKV + (size_t)l * QKVS,          bq + (size_t)l * CC, CC * 4, cudaMemcpyDeviceToDevice);
            cudaMemcpyAsync(BQKV + (size_t)l * QKVS + CC,     bk + (size_t)l * CC, CC * 4, cudaMemcpyDeviceToDevice);
            cudaMemcpyAsync(BQKV + (size_t)l * QKVS + 2 * CC, bv + (size_t)l * CC, CC * 4, cudaMemcpyDeviceToDevice);
        }
        round_tf32_kernel<<<(unsigned)((nqk + 255) / 256), 256>>>(Wo, RWO, nqk);
        round_tf32_kernel<<<(unsigned)((nm + 255) / 256), 256>>>(W1, RW1, nm);
        round_tf32_kernel<<<(unsigned)((nm + 255) / 256), 256>>>(W2, RW2, nm);
        round_tf32_kernel<<<(unsigned)((ne + 255) / 256), 256>>>(tok_emb, REMB, ne);
    }

    embed_kernel<<<MM, 256>>>(tok_emb, cls_emb, pos_emb, idx_tok, idx_cls, X);

    const int SM_DYN = 3 * SLAB_BYTES;   // 49152
    dim3 gQkv(QKVS / 128, (MM + 127) / 128);     // (24, 65)
    dim3 gProj(CC / 128, (MM + 127) / 128);      // (8, 65)
    dim3 gMlp1(C4 / 128, (MM + 127) / 128);      // (32, 65)
    dim3 gMlp2(CC / 128, (MM + 127) / 128);
    dim3 gLogit(VV / 128, (MM + 127) / 128);     // (128, 65)
    dim3 gFlash(9, BB * NHH);

    for (int l = 0; l < LL; l++) {
        const float* l1w   = ln1_w + (size_t)l * CC;
        const float* l1b   = ln1_b + (size_t)l * CC;
        const float* rwqkv = RWQKV + (size_t)l * QKVS * CC;
        const float* bqkvl = BQKV + (size_t)l * QKVS;
        const float* rwo   = RWO + (size_t)l * CC * CC;
        const float* bol   = bo + (size_t)l * CC;
        const float* l2w   = ln2_w + (size_t)l * CC;
        const float* l2b   = ln2_b + (size_t)l * CC;
        const float* rw1   = RW1 + (size_t)l * C4 * CC;
        const float* b1l   = b1 + (size_t)l * C4;
        const float* rw2   = RW2 + (size_t)l * CC * C4;
        const float* b2l   = b2 + (size_t)l * CC;

        layernorm_kernel<<<MM, 256>>>(X, l1w, l1b, H);

        // fused QKV projection: [MM, 3072]
        tgemm_nt<false,false><<<gQkv, 256, SM_DYN>>>(H, rwqkv, bqkvl, nullptr, QKV, MM, QKVS, CC);

        flash_attn_kernel<<<gFlash, 256>>>(QKV, Y);

        tgemm_nt<true,false><<<gProj, 256, SM_DYN>>>(Y, rwo, bol, X, X, MM, CC, CC);

        layernorm_kernel<<<MM, 256>>>(X, l2w, l2b, H);
        tgemm_nt<false,true><<<gMlp1, 256, SM_DYN>>>(H, rw1, b1l, nullptr, MLP, MM, C4, CC);
        tgemm_nt<true,false><<<gMlp2, 256, SM_DYN>>>(MLP, rw2, b2l, X, X, MM, CC, C4);
    }

    layernorm_kernel<<<MM, 256>>>(X, lnf_w, lnf_b, H);
    tgemm_nt<false,false><<<gLogit, 256, SM_DYN>>>(H, REMB, nullptr, nullptr, out, MM, VV, CC);
}